// round 7
// baseline (speedup 1.0000x reference)
#include <cuda_runtime.h>

#define NTRAJ 2048
#define TSTEPS 512
#define KDIM   (TSTEPS * 3)
#define PF 8

// Transposed measurements: [t*3+k][traj]. 12 MB.
__device__ float g_zt[KDIM * NTRAJ];
// Dump target for non-writer lanes (branch-free store). Never read.
__device__ float2 g_dump[128 * 64];

__global__ void transpose_k(const float* __restrict__ meas) {
    __shared__ float tile[32][33];
    int rem0  = blockIdx.x * 32;
    int traj0 = blockIdx.y * 32;
    tile[threadIdx.y][threadIdx.x] = meas[(traj0 + threadIdx.y) * KDIM + rem0 + threadIdx.x];
    __syncthreads();
    g_zt[(rem0 + threadIdx.y) * NTRAJ + traj0 + threadIdx.x] = tile[threadIdx.x][threadIdx.y];
}

__device__ __forceinline__ float htanh(float x) {
    float y;
    asm("tanh.approx.f32 %0, %1;" : "=f"(y) : "f"(x));
    return y;
}
// rcp.approx + 1 Newton step: matches IEEE 1/x to <=1 ulp.
__device__ __forceinline__ float frcp_nr(float x) {
    float y;
    asm("rcp.approx.f32 %0, %1;" : "=f"(y) : "f"(x));
    float e = fmaf(-x, y, 1.0f);
    return fmaf(e, y, y);
}

// One 2x2 Kalman step (no cross-lane part). Outputs S and mah.
__device__ __forceinline__ void kcore(
    float& s0, float& s1, float& p00, float& p01, float& p11,
    float z, float dt, float c1, float c2, float c3, float c4,
    float q0, float q1, float r, float& S, float& mah)
{
    float sp = fmaf(dt, s1, s0);
    float tv = htanh(100.0f * s1);
    float vp = fmaf(-c2, tv, c1 * s1);
    float a  = fmaf(c3, tv * tv, c4);

    float u   = fmaf(dt, p11, p01);
    float n00 = fmaf(dt, u, fmaf(dt, p01, p00)) + q0;
    float n01 = a * u;
    float n11 = fmaf(a * a, p11, q1);

    S = n00 + r;
    float is = frcp_nr(S);
    float yv = z - sp;
    float K0 = __fmul_rn(n00, is);
    float K1 = __fmul_rn(n01, is);
    s0 = fmaf(K0, yv, sp);
    s1 = fmaf(K1, yv, vp);
    float om = 1.0f - K0;
    p00 = om * n00;
    p01 = om * n01;
    p11 = fmaf(-K1, n01, n11);
    mah = yv * (is * yv);
}

__device__ __forceinline__ float combine(float S, float mah) {
    float S8  = __shfl_down_sync(0xFFFFFFFFu, S, 8);
    float S16 = __shfl_down_sync(0xFFFFFFFFu, S, 16);
    float m8  = __shfl_down_sync(0xFFFFFFFFu, mah, 8);
    float m16 = __shfl_down_sync(0xFFFFFFFFu, mah, 16);
    return fmaf(S * S8, S16, (mah + m8) + m16);
}

// One warp = 16 trajectories. Lanes (c = lane>>3, j = lane&7) each run TWO
// independent chains (traj j and traj j+8): chain B's instructions fill
// chain A's latency stalls. launch_bounds(32,1) prevents the reg-cap spills
// that killed the previous ILP attempt.
__global__ void __launch_bounds__(32, 1) ekf_k(
    const float* __restrict__ init_state,
    const float* __restrict__ dyna,
    const float* __restrict__ Q,
    const float* __restrict__ R,
    const float* __restrict__ P0,
    float* __restrict__ out)
{
    const int lane = threadIdx.x & 31;
    int c = lane >> 3; if (c > 2) c = 2;
    const int j     = lane & 7;
    const int trajA = blockIdx.x * 16 + j;
    const int trajB = trajA + 8;

    const float dt = 1.0f / 120.0f;

    const bool lin = (c == 2);
    const float fric = lin ? 0.0f : __ldg(dyna + 0);
    const float damp = lin ? 0.0f : __ldg(dyna + 1);

    const float c1 = 1.0f - dt * damp;
    const float c2 = dt * fric;
    const float c3 = 100.0f * c2;
    const float c4 = c1 - c3;

    const int pc = lin ? 4 : c;
    const int vc = lin ? 5 : c + 2;

    const float q0 = __ldg(Q + pc * 7);
    const float q1 = __ldg(Q + vc * 7);
    const float r  = __ldg(R + c * 4);

    float s0A = init_state[trajA * 6 + pc], s1A = init_state[trajA * 6 + vc];
    float s0B = init_state[trajB * 6 + pc], s1B = init_state[trajB * 6 + vc];

    const float P0a = __ldg(P0 + pc * 7);
    const float P0b = __ldg(P0 + pc * 6 + vc);
    const float P0c = __ldg(P0 + vc * 7);
    float p00A = P0a, p01A = P0b, p11A = P0c;
    float p00B = P0a, p01B = P0b, p11B = P0c;

    const float* zbA = g_zt + c * NTRAJ + trajA;
    const float* zbB = g_zt + c * NTRAJ + trajB;
    float* oA = out + trajA * TSTEPS;
    float* oB = out + trajB * TSTEPS;
    float2* dump = g_dump + (blockIdx.x * 64 + lane * 2);

    float zrA[PF], zrB[PF];
    #pragma unroll
    for (int i = 0; i < PF; ++i) {
        zrA[i] = zbA[3 * i * NTRAJ];
        zrB[i] = zbB[3 * i * NTRAJ];
    }

    float lpA, lpB;

    #pragma unroll 1
    for (int t = 0; t < TSTEPS; t += PF) {
        #pragma unroll
        for (int u8 = 0; u8 < PF; ++u8) {
            const int t_ = t + u8;
            float zA = zrA[u8];
            float zB = zrB[u8];

            // unconditional prefetch, clamped address (tail loads unused)
            int tn = t_ + PF; tn = (tn > TSTEPS - 1) ? (TSTEPS - 1) : tn;
            zrA[u8] = zbA[3 * tn * NTRAJ];
            zrB[u8] = zbB[3 * tn * NTRAJ];

            float SA, MA, SB, MB;
            kcore(s0A, s1A, p00A, p01A, p11A, zA,
                  dt, c1, c2, c3, c4, q0, q1, r, SA, MA);
            kcore(s0B, s1B, p00B, p01B, p11B, zB,
                  dt, c1, c2, c3, c4, q0, q1, r, SB, MB);

            float lossA = combine(SA, MA);
            float lossB = combine(SB, MB);

            if ((u8 & 1) == 0) {
                lpA = lossA; lpB = lossB;
            } else {
                // branch-free float2 stores: writer lanes -> out, rest -> dump
                float2* dA = (lane < 8)
                           ? reinterpret_cast<float2*>(oA + (t_ - 1)) : dump;
                float2* dB = (lane < 8)
                           ? reinterpret_cast<float2*>(oB + (t_ - 1)) : (dump + 1);
                *dA = make_float2(lpA, lossA);
                *dB = make_float2(lpB, lossB);
            }
        }
    }
}

extern "C" void kernel_launch(void* const* d_in, const int* in_sizes, int n_in,
                              void* d_out, int out_size) {
    const float* meas = (const float*)d_in[0];
    const float* init = (const float*)d_in[1];
    const float* dyna = (const float*)d_in[2];
    const float* Q    = (const float*)d_in[3];
    const float* R    = (const float*)d_in[4];
    const float* P0   = (const float*)d_in[5];
    float* out = (float*)d_out;

    dim3 tgrid(KDIM / 32, NTRAJ / 32);
    dim3 tblk(32, 32);
    transpose_k<<<tgrid, tblk>>>(meas);
    ekf_k<<<NTRAJ / 16, 32>>>(init, dyna, Q, R, P0, out);
}

// round 9
// speedup vs baseline: 1.1731x; 1.1731x over previous
#include <cuda_runtime.h>

#define NTRAJ  2048
#define TSTEPS 512
#define KDIM   (TSTEPS * 3)
#define NCH    (3 * NTRAJ)     // 6144 independent 2x2 Kalman chains
#define PF     8
#define DT     0.00833333333333333f

// Transposed measurements: [t*3+k][traj]. 12 MB.
__device__ float  g_zt[KDIM * NTRAJ];
// Per-(t, chain) partials (S, mah). 25 MB.
__device__ float2 g_part[TSTEPS * NCH];

__global__ void transpose_k(const float* __restrict__ meas) {
    __shared__ float tile[32][33];
    int rem0  = blockIdx.x * 32;
    int traj0 = blockIdx.y * 32;
    tile[threadIdx.y][threadIdx.x] = meas[(traj0 + threadIdx.y) * KDIM + rem0 + threadIdx.x];
    __syncthreads();
    g_zt[(rem0 + threadIdx.y) * NTRAJ + traj0 + threadIdx.x] = tile[threadIdx.x][threadIdx.y];
}

__device__ __forceinline__ float htanh(float x) {
    float y;
    asm("tanh.approx.f32 %0, %1;" : "=f"(y) : "f"(x));
    return y;
}
__device__ __forceinline__ float frcp(float x) {
    float y;
    asm("rcp.approx.f32 %0, %1;" : "=f"(y) : "f"(x));
    return y;
}

// One scalar-observation 2x2 Kalman step. Uses 1-K0 == r*is identity
// (cancellation-free), so raw rcp.approx is numerically safe.
__device__ __forceinline__ void kstep(
    float& s0, float& s1, float& p00, float& p01, float& p11,
    float z, float c1, float c2, float c3, float c4,
    float q0, float q1, float r, float& S_out, float& M_out)
{
    float sp = fmaf(DT, s1, s0);
    float tv = htanh(100.0f * s1);
    float vp = fmaf(-c2, tv, c1 * s1);
    float a  = fmaf(c3, tv * tv, c4);

    float u   = fmaf(DT, p11, p01);
    float n00 = fmaf(DT, u, fmaf(DT, p01, p00)) + q0;
    float n01 = a * u;
    float n11 = fmaf(a * a, p11, q1);

    float S  = n00 + r;
    float is = frcp(S);
    float yv = z - sp;
    float K0 = __fmul_rn(n00, is);
    float K1 = __fmul_rn(n01, is);
    s0 = fmaf(K0, yv, sp);
    s1 = fmaf(K1, yv, vp);
    p00 = __fmul_rn(r * n00, is);
    p01 = __fmul_rn(r * n01, is);
    p11 = fmaf(-__fmul_rn(n01, n01), is, n11);

    S_out = S;
    M_out = yv * (is * yv);
}

// 6144 chains, one per lane. chain = c*2048 + traj keeps z-loads and
// partial-stores coalesced. No shuffles, no branches in the mainloop.
__global__ void __launch_bounds__(32, 1) ekf_k(
    const float* __restrict__ init_state,
    const float* __restrict__ dyna,
    const float* __restrict__ Q,
    const float* __restrict__ R,
    const float* __restrict__ P0)
{
    const int lane  = threadIdx.x & 31;
    const int chain = blockIdx.x * 32 + lane;
    const int c     = chain >> 11;          // 0,1,2
    const int traj  = chain & (NTRAJ - 1);

    const bool lin = (c == 2);
    const float fric = lin ? 0.0f : __ldg(dyna + 0);
    const float damp = lin ? 0.0f : __ldg(dyna + 1);

    const float c1 = 1.0f - DT * damp;
    const float c2 = DT * fric;
    const float c3 = 100.0f * c2;
    const float c4 = c1 - c3;

    const int pc = lin ? 4 : c;
    const int vc = lin ? 5 : c + 2;

    const float q0 = __ldg(Q + pc * 7);
    const float q1 = __ldg(Q + vc * 7);
    const float r  = __ldg(R + c * 4);

    float s0 = init_state[traj * 6 + pc];
    float s1 = init_state[traj * 6 + vc];

    float p00 = __ldg(P0 + pc * 7);
    float p01 = __ldg(P0 + pc * 6 + vc);
    float p11 = __ldg(P0 + vc * 7);

    const float* zb = g_zt + c * NTRAJ + traj;
    float2*      pp = g_part + chain;

    float zr[PF];
    #pragma unroll
    for (int i = 0; i < PF; ++i) zr[i] = zb[3 * i * NTRAJ];

    const float* pz = zb + 3 * PF * NTRAJ;

    // main loop: 504 steps with unconditional prefetch (max step loaded = 511)
    #pragma unroll 1
    for (int t = 0; t < TSTEPS - PF; t += PF) {
        #pragma unroll
        for (int u8 = 0; u8 < PF; ++u8) {
            float z = zr[u8];
            zr[u8] = pz[3 * u8 * NTRAJ];
            float S, M;
            kstep(s0, s1, p00, p01, p11, z, c1, c2, c3, c4, q0, q1, r, S, M);
            pp[u8 * NCH] = make_float2(S, M);
        }
        pz += 3 * PF * NTRAJ;
        pp += PF * NCH;
    }
    // tail: last 8 steps, no prefetch
    #pragma unroll
    for (int u8 = 0; u8 < PF; ++u8) {
        float S, M;
        kstep(s0, s1, p00, p01, p11, zr[u8], c1, c2, c3, c4, q0, q1, r, S, M);
        pp[u8 * NCH] = make_float2(S, M);
    }
}

// loss[traj][t] = (Sx*Sy)*St + (mx+my)+mt, smem-transposed so both the
// partial loads and the output stores are coalesced.
__global__ void combine_k(float* __restrict__ out) {
    __shared__ float tile[32][33];
    const int t0  = blockIdx.x * 32;
    const int tr0 = blockIdx.y * 32;
    const int tx = threadIdx.x, ty = threadIdx.y;

    const float2* base = g_part + (t0 + ty) * NCH + tr0 + tx;
    float2 px = base[0];
    float2 py = base[NTRAJ];
    float2 pt = base[2 * NTRAJ];
    tile[ty][tx] = fmaf(px.x * py.x, pt.x, (px.y + py.y) + pt.y);
    __syncthreads();
    out[(tr0 + ty) * TSTEPS + t0 + tx] = tile[tx][ty];
}

extern "C" void kernel_launch(void* const* d_in, const int* in_sizes, int n_in,
                              void* d_out, int out_size) {
    const float* meas = (const float*)d_in[0];
    const float* init = (const float*)d_in[1];
    const float* dyna = (const float*)d_in[2];
    const float* Q    = (const float*)d_in[3];
    const float* R    = (const float*)d_in[4];
    const float* P0   = (const float*)d_in[5];
    float* out = (float*)d_out;

    dim3 tgrid(KDIM / 32, NTRAJ / 32);
    dim3 tblk(32, 32);
    transpose_k<<<tgrid, tblk>>>(meas);
    ekf_k<<<NCH / 32, 32>>>(init, dyna, Q, R, P0);
    dim3 cgrid(TSTEPS / 32, NTRAJ / 32);
    combine_k<<<cgrid, tblk>>>(out);
}

// round 10
// speedup vs baseline: 1.6344x; 1.3932x over previous
#include <cuda_runtime.h>

#define NTRAJ  2048
#define TSTEPS 512
#define KDIM   (TSTEPS * 3)
#define NCH    (3 * NTRAJ)     // 6144 independent 2x2 Kalman chains
#define PF     8
#define DT     0.00833333333333333f

// Per-(t, chain) partials (S, mah). 25 MB; L2-resident between kernels.
__device__ float2 g_part[TSTEPS * NCH];

__device__ __forceinline__ float htanh(float x) {
    float y;
    asm("tanh.approx.f32 %0, %1;" : "=f"(y) : "f"(x));
    return y;
}
// rcp.approx + 1 Newton step: <=1 ulp vs IEEE, keeps the 512-step recursion tight.
__device__ __forceinline__ float frcp_nr(float x) {
    float y;
    asm("rcp.approx.f32 %0, %1;" : "=f"(y) : "f"(x));
    float e = fmaf(-x, y, 1.0f);
    return fmaf(e, y, y);
}

// One scalar-observation 2x2 Kalman step. 1-K0 == r*is identity -> no
// catastrophic cancellation anywhere.
__device__ __forceinline__ void kstep(
    float& s0, float& s1, float& p00, float& p01, float& p11,
    float z, float c1, float c2, float c3, float c4,
    float q0, float q1, float r, float& S_out, float& M_out)
{
    float sp = fmaf(DT, s1, s0);
    float tv = htanh(100.0f * s1);
    float vp = fmaf(-c2, tv, c1 * s1);
    float a  = fmaf(c3, tv * tv, c4);

    float u   = fmaf(DT, p11, p01);
    float n00 = fmaf(DT, u, fmaf(DT, p01, p00)) + q0;
    float n01 = a * u;
    float n11 = fmaf(a * a, p11, q1);

    float S  = n00 + r;
    float is = frcp_nr(S);
    float yv = z - sp;
    float K0 = __fmul_rn(n00, is);
    float K1 = __fmul_rn(n01, is);
    s0 = fmaf(K0, yv, sp);
    s1 = fmaf(K1, yv, vp);
    p00 = __fmul_rn(r * n00, is);
    p01 = __fmul_rn(r * n01, is);
    p11 = fmaf(-__fmul_rn(n01, n01), is, n11);

    S_out = S;
    M_out = yv * (is * yv);
}

// 6144 chains, one per lane (192 warps). z is read DIRECTLY from the original
// [traj][t][k] layout: per-lane 12-byte stride means ~10 consecutive steps hit
// the same L1 line, so no separate transpose pass is needed.
__global__ void __launch_bounds__(32, 1) ekf_k(
    const float* __restrict__ meas,
    const float* __restrict__ init_state,
    const float* __restrict__ dyna,
    const float* __restrict__ Q,
    const float* __restrict__ R,
    const float* __restrict__ P0)
{
    const int lane  = threadIdx.x & 31;
    const int chain = blockIdx.x * 32 + lane;
    const int c     = chain >> 11;          // 0,1,2
    const int traj  = chain & (NTRAJ - 1);

    const bool lin = (c == 2);
    const float fric = lin ? 0.0f : __ldg(dyna + 0);
    const float damp = lin ? 0.0f : __ldg(dyna + 1);

    const float c1 = 1.0f - DT * damp;
    const float c2 = DT * fric;
    const float c3 = 100.0f * c2;
    const float c4 = c1 - c3;

    const int pc = lin ? 4 : c;
    const int vc = lin ? 5 : c + 2;

    const float q0 = __ldg(Q + pc * 7);
    const float q1 = __ldg(Q + vc * 7);
    const float r  = __ldg(R + c * 4);

    float s0 = init_state[traj * 6 + pc];
    float s1 = init_state[traj * 6 + vc];

    float p00 = __ldg(P0 + pc * 7);
    float p01 = __ldg(P0 + pc * 6 + vc);
    float p11 = __ldg(P0 + vc * 7);

    const float* zb = meas + traj * KDIM + c;   // z(t) at zb[3*t]
    float2*      pp = g_part + chain;

    float zr[PF];
    #pragma unroll
    for (int i = 0; i < PF; ++i) zr[i] = zb[3 * i];

    const float* pz = zb + 3 * PF;

    // main loop: 504 steps with unconditional prefetch (max step loaded = 511)
    #pragma unroll 1
    for (int t = 0; t < TSTEPS - PF; t += PF) {
        #pragma unroll
        for (int u8 = 0; u8 < PF; ++u8) {
            float z = zr[u8];
            zr[u8] = pz[3 * u8];
            float S, M;
            kstep(s0, s1, p00, p01, p11, z, c1, c2, c3, c4, q0, q1, r, S, M);
            pp[u8 * NCH] = make_float2(S, M);
        }
        pz += 3 * PF;
        pp += PF * NCH;
    }
    // tail: last 8 steps, no prefetch
    #pragma unroll
    for (int u8 = 0; u8 < PF; ++u8) {
        float S, M;
        kstep(s0, s1, p00, p01, p11, zr[u8], c1, c2, c3, c4, q0, q1, r, S, M);
        pp[u8 * NCH] = make_float2(S, M);
    }
}

// loss[traj][t] = (Sx*Sy)*St + (mx+my)+mt, smem-transposed so both the
// partial loads and the output stores are coalesced.
__global__ void combine_k(float* __restrict__ out) {
    __shared__ float tile[32][33];
    const int t0  = blockIdx.x * 32;
    const int tr0 = blockIdx.y * 32;
    const int tx = threadIdx.x, ty = threadIdx.y;

    const float2* base = g_part + (t0 + ty) * NCH + tr0 + tx;
    float2 px = base[0];
    float2 py = base[NTRAJ];
    float2 pt = base[2 * NTRAJ];
    tile[ty][tx] = fmaf(px.x * py.x, pt.x, (px.y + py.y) + pt.y);
    __syncthreads();
    out[(tr0 + ty) * TSTEPS + t0 + tx] = tile[tx][ty];
}

extern "C" void kernel_launch(void* const* d_in, const int* in_sizes, int n_in,
                              void* d_out, int out_size) {
    const float* meas = (const float*)d_in[0];
    const float* init = (const float*)d_in[1];
    const float* dyna = (const float*)d_in[2];
    const float* Q    = (const float*)d_in[3];
    const float* R    = (const float*)d_in[4];
    const float* P0   = (const float*)d_in[5];
    float* out = (float*)d_out;

    ekf_k<<<NCH / 32, 32>>>(meas, init, dyna, Q, R, P0);
    dim3 cgrid(TSTEPS / 32, NTRAJ / 32);
    combine_k<<<cgrid, dim3(32, 32)>>>(out);
}